// round 9
// baseline (speedup 1.0000x reference)
#include <cuda_runtime.h>
#include <cuda_bf16.h>
#include <cstdint>

#define B_TOTAL 262144
#define IN_DIM 28
#define HID 128
#define LAT 64
#define NCODES 512
#define GRID1 148
#define TILE_M 128
#define NTILES (B_TOTAL / TILE_M)   // 2048

#define ETHREADS 512
#define EWARPS 16

// ---- k_encode smem layout (bytes) ----
#define OF_CBL   0                      // codebook lo bf16, 512x128B = 65536
#define OF_XBH   65536                  // x hi bf16, 128x64B = 8192
#define OF_XBL   73728                  // x lo
#define OF_ZBH   81920                  // z hi, 128x128B = 16384 (CBH staging at init)
#define OF_ZBL   98304                  // z lo
#define OF_ZP    114688                 // partial-z exchange fp32[128][66] = 33792
#define OF_W2    148480                 // W2H0,W2H1,W2L0,W2L1 (8K each) = 32768
#define OF_W1TH  181248                 // W1^T hi [128n][32k] 64B rows = 8192
#define OF_W1TL  189440                 // 8192
#define OF_B1    197632                 // 512
#define OF_B2    198144                 // 256
#define OF_E2    198400                 // 2048
#define OF_CAND  200448                 // u64[128] = 1024
#define OF_Z2    201472                 // float[128][2] = 1024
#define SMEM_E   202496

// XOR swizzle, 128B rows (16B granularity)
#define SWZ_W(row, w)  ((row) * 128 + ((((w) >> 2) ^ ((row) & 7)) << 4) + ((w) & 3) * 4)
#define SWZ_C(row, ch) ((row) * 128 + ((((ch)) ^ ((row) & 7)) << 4))
// XOR swizzle, 64B rows
#define SWZ64_W(row, w)  ((row) * 64 + ((((w) >> 2) ^ (((row) >> 1) & 3)) << 4) + ((w) & 3) * 4)
#define SWZ64_C(row, ch) ((row) * 64 + ((((ch)) ^ (((row) >> 1) & 3)) << 4))

#define ZP_STRIDE 66

#define KOUT_GRID 592

__device__ int    g_idx[B_TOTAL];
__device__ float  g_vq_part[GRID1];
__device__ float  g_rec_part[KOUT_GRID];
__device__ float  g_hd[NCODES * HID];
__device__ float  g_tbl[NCODES * IN_DIM];

// ---------------- helpers ----------------
__device__ __forceinline__ uint32_t smem_u32_of(const void* p) {
    uint32_t a;
    asm("{ .reg .u64 t; cvta.to.shared.u64 t, %1; cvt.u32.u64 %0, t; }" : "=r"(a) : "l"(p));
    return a;
}
__device__ __forceinline__ void ldsm_x4(uint32_t* r, uint32_t addr) {
    asm volatile("ldmatrix.sync.aligned.m8n8.x4.shared.b16 {%0,%1,%2,%3}, [%4];"
        : "=r"(r[0]), "=r"(r[1]), "=r"(r[2]), "=r"(r[3]) : "r"(addr));
}
__device__ __forceinline__ void mma16816(float* d, const uint32_t* a, uint32_t b0, uint32_t b1) {
    asm volatile("mma.sync.aligned.m16n8k16.row.col.f32.bf16.bf16.f32 "
        "{%0,%1,%2,%3}, {%4,%5,%6,%7}, {%8,%9}, {%0,%1,%2,%3};"
        : "+f"(d[0]), "+f"(d[1]), "+f"(d[2]), "+f"(d[3])
        : "r"(a[0]), "r"(a[1]), "r"(a[2]), "r"(a[3]), "r"(b0), "r"(b1));
}
__device__ __forceinline__ void bf16_split(float v, __nv_bfloat16& hi, __nv_bfloat16& lo) {
    hi = __float2bfloat16(v);
    lo = __float2bfloat16(v - __bfloat162float(hi));
}
__device__ __forceinline__ uint32_t pack2_split_hi(float a, float b, uint32_t& lo_out) {
    __nv_bfloat16 ha, la, hb, lb;
    bf16_split(a, ha, la); bf16_split(b, hb, lb);
    __nv_bfloat162 ph; ph.x = ha; ph.y = hb;
    __nv_bfloat162 pl; pl.x = la; pl.y = lb;
    lo_out = *(uint32_t*)&pl;
    return *(uint32_t*)&ph;
}
// monotone key: smaller distance first, then smaller index
__device__ __forceinline__ unsigned long long dist_key(float d, int c) {
    uint32_t u = __float_as_uint(d);
    u ^= (uint32_t)((int32_t)u >> 31) | 0x80000000u;
    return ((unsigned long long)u << 32) | (uint32_t)c;
}
__device__ __forceinline__ float dist_unkey(unsigned long long key) {
    uint32_t u = (uint32_t)(key >> 32);
    u = (u & 0x80000000u) ? (u ^ 0x80000000u) : ~u;
    return __uint_as_float(u);
}

// ============================================================================
// K1: encoder — reg-fused enc1->enc2 MMA, distance MMA w/ reg-resident CBH
// ============================================================================
__global__ void __launch_bounds__(ETHREADS, 1)
k_encode(const float* __restrict__ x,
         const float* __restrict__ w1, const float* __restrict__ b1,
         const float* __restrict__ w2, const float* __restrict__ b2,
         const float* __restrict__ cb)
{
    extern __shared__ char smem[];
    const uint32_t smb = smem_u32_of(smem);

    float* s_b1 = (float*)(smem + OF_B1);
    float* s_b2 = (float*)(smem + OF_B2);
    float* s_e2 = (float*)(smem + OF_E2);
    float* s_z2 = (float*)(smem + OF_Z2);
    float* s_zp = (float*)(smem + OF_ZP);
    unsigned long long* s_cand = (unsigned long long*)(smem + OF_CAND);

    const int tid = threadIdx.x;
    const int warp = tid >> 5, lane = tid & 31;

    // ---- init ----
    for (int i = tid; i < HID; i += ETHREADS) s_b1[i] = b1[i];
    for (int i = tid; i < LAT; i += ETHREADS) s_b2[i] = b2[i];
    // codebook split: hi -> staging (at ZB region), lo -> CBL (128B rows)
    for (int i = tid; i < NCODES * 32; i += ETHREADS) {
        int c = i >> 5, w = i & 31;
        uint32_t lo;
        uint32_t hi = pack2_split_hi(cb[c * LAT + 2 * w], cb[c * LAT + 2 * w + 1], lo);
        *(uint32_t*)(smem + OF_ZBH + SWZ_W(c, w)) = hi;   // staging
        *(uint32_t*)(smem + OF_CBL + SWZ_W(c, w)) = lo;
    }
    // W2^T split: [64 n][128 k] as two k-halves, 128B rows
    for (int i = tid; i < LAT * 64; i += ETHREADS) {
        int n = i >> 6, kw = i & 63;
        uint32_t lo;
        uint32_t hi = pack2_split_hi(w2[2 * kw * LAT + n], w2[(2 * kw + 1) * LAT + n], lo);
        int khalf = kw >> 5, w = kw & 31;
        *(uint32_t*)(smem + OF_W2 + khalf * 8192 + SWZ_W(n, w))         = hi;
        *(uint32_t*)(smem + OF_W2 + 16384 + khalf * 8192 + SWZ_W(n, w)) = lo;
    }
    // W1^T split: [128 n][32 k], 64B rows; zero-pad k 28..31
    for (int i = tid; i < HID * 14; i += ETHREADS) {
        int n = i / 14, kw = i - n * 14;
        uint32_t lo;
        uint32_t hi = pack2_split_hi(w1[2 * kw * HID + n], w1[(2 * kw + 1) * HID + n], lo);
        *(uint32_t*)(smem + OF_W1TH + SWZ64_W(n, kw)) = hi;
        *(uint32_t*)(smem + OF_W1TL + SWZ64_W(n, kw)) = lo;
    }
    for (int i = tid; i < HID * 2; i += ETHREADS) {
        int n = i >> 1, w = 14 + (i & 1);
        *(uint32_t*)(smem + OF_W1TH + SWZ64_W(n, w)) = 0;
        *(uint32_t*)(smem + OF_W1TL + SWZ64_W(n, w)) = 0;
    }
    // XB k-pad (words 14,15), static across tiles
    for (int i = tid; i < TILE_M * 2; i += ETHREADS) {
        int row = i >> 1, w = 14 + (i & 1);
        *(uint32_t*)(smem + OF_XBH + SWZ64_W(row, w)) = 0;
        *(uint32_t*)(smem + OF_XBL + SWZ64_W(row, w)) = 0;
    }
    for (int c = tid; c < NCODES; c += ETHREADS) {
        float s = 0.f;
        for (int k = 0; k < LAT; k++) { float v = cb[c * LAT + k]; s = fmaf(v, v, s); }
        s_e2[c] = s;
    }
    if (tid < TILE_M) s_cand[tid] = ~0ULL;
    __syncthreads();

    // mma lane-role constants
    const int g = lane >> 2, t = lane & 3;
    const int a_roff = (lane & 7) + 8 * ((lane >> 3) & 1);
    const int a_ch   = lane >> 4;
    const int b_row0 = (lane & 7) + 8 * ((lane >> 4) & 1);
    const int b_ch   = (lane >> 3) & 1;

    // ---- this warp's CBH fragments -> registers (from staging) ----
    uint32_t bregH[4][4][2];
    #pragma unroll
    for (int pp = 0; pp < 2; pp++)
        #pragma unroll
        for (int kk = 0; kk < 4; kk++) {
            uint32_t r4[4];
            ldsm_x4(r4, smb + OF_ZBH + SWZ_C(warp * 32 + pp * 16 + b_row0, 2 * kk + b_ch));
            bregH[2 * pp][kk][0] = r4[0];     bregH[2 * pp][kk][1] = r4[1];
            bregH[2 * pp + 1][kk][0] = r4[2]; bregH[2 * pp + 1][kk][1] = r4[3];
        }
    __syncthreads();   // staging region (ZB/ZP) now free

    const int rbw = warp >> 1, nhf = warp & 1;
    const int R0w = rbw * 16;
    const int rA = R0w + g, rB = rA + 8;
    float vq_local = 0.f;

    for (int tle = blockIdx.x; tle < NTILES; tle += GRID1) {
        // -------- P0: stage x into XB hi/lo --------
        {
            const float4* xg4 = (const float4*)(x + (long)tle * TILE_M * IN_DIM);
            #pragma unroll
            for (int it = 0; it < 2; it++) {
                int i = tid + it * ETHREADS;
                if (i < TILE_M * 7) {
                    int row = i / 7, w4 = i - row * 7;
                    float4 v = xg4[i];
                    uint32_t lo0, lo1;
                    uint32_t hi0 = pack2_split_hi(v.x, v.y, lo0);
                    uint32_t hi1 = pack2_split_hi(v.z, v.w, lo1);
                    uint64_t hp = (uint64_t)hi0 | ((uint64_t)hi1 << 32);
                    uint64_t lp = (uint64_t)lo0 | ((uint64_t)lo1 << 32);
                    *(uint64_t*)(smem + OF_XBH + SWZ64_W(row, 2 * w4)) = hp;
                    *(uint64_t*)(smem + OF_XBL + SWZ64_W(row, 2 * w4)) = lp;
                }
            }
        }
        __syncthreads();   // A

        // -------- P1: enc1 MMA; h C-frags -> P2 A-frags in registers --------
        uint32_t aH[4][4], aL[4][4];
        {
            float acc[8][4];
            #pragma unroll
            for (int nb = 0; nb < 8; nb++)
                #pragma unroll
                for (int u = 0; u < 4; u++) acc[nb][u] = 0.f;

            #pragma unroll
            for (int kk = 0; kk < 2; kk++) {
                uint32_t xH[4], xL[4];
                uint32_t offA = SWZ64_C(R0w + a_roff, 2 * kk + a_ch);
                ldsm_x4(xH, smb + OF_XBH + offA);
                ldsm_x4(xL, smb + OF_XBL + offA);
                #pragma unroll
                for (int pp = 0; pp < 4; pp++) {
                    int nrow = nhf * 64 + pp * 16 + b_row0;
                    uint32_t offB = SWZ64_C(nrow, 2 * kk + b_ch);
                    uint32_t bH[4], bL[4];
                    ldsm_x4(bH, smb + OF_W1TH + offB);
                    ldsm_x4(bL, smb + OF_W1TL + offB);
                    mma16816(acc[2 * pp], xH, bH[0], bH[1]);
                    mma16816(acc[2 * pp], xH, bL[0], bL[1]);
                    mma16816(acc[2 * pp], xL, bH[0], bH[1]);
                    mma16816(acc[2 * pp + 1], xH, bH[2], bH[3]);
                    mma16816(acc[2 * pp + 1], xH, bL[2], bL[3]);
                    mma16816(acc[2 * pp + 1], xL, bH[2], bH[3]);
                }
            }
            // epilogue: bias+relu, split directly into A-fragments
            #pragma unroll
            for (int nb = 0; nb < 8; nb++) {
                int c = nhf * 64 + nb * 8 + 2 * t;
                float bb0 = s_b1[c], bb1 = s_b1[c + 1];
                float h0 = fmaxf(acc[nb][0] + bb0, 0.f);
                float h1 = fmaxf(acc[nb][1] + bb1, 0.f);
                float h2 = fmaxf(acc[nb][2] + bb0, 0.f);
                float h3 = fmaxf(acc[nb][3] + bb1, 0.f);
                int kc = nb >> 1, hf = nb & 1;
                aH[kc][2 * hf]     = pack2_split_hi(h0, h1, aL[kc][2 * hf]);
                aH[kc][2 * hf + 1] = pack2_split_hi(h2, h3, aL[kc][2 * hf + 1]);
            }
        }

        // -------- P2a: enc2 partial MMA over this warp's k-half, all 64 n --------
        float acc2[8][4];
        #pragma unroll
        for (int nb = 0; nb < 8; nb++)
            #pragma unroll
            for (int u = 0; u < 4; u++) acc2[nb][u] = 0.f;

        #pragma unroll
        for (int kk = 0; kk < 4; kk++) {
            #pragma unroll
            for (int pp = 0; pp < 4; pp++) {
                int nrow = pp * 16 + b_row0;
                uint32_t offB = SWZ_C(nrow, 2 * kk + b_ch);
                uint32_t bH[4], bL[4];
                ldsm_x4(bH, smb + OF_W2 + nhf * 8192 + offB);
                ldsm_x4(bL, smb + OF_W2 + 16384 + nhf * 8192 + offB);
                mma16816(acc2[2 * pp], aH[kk], bH[0], bH[1]);
                mma16816(acc2[2 * pp], aH[kk], bL[0], bL[1]);
                mma16816(acc2[2 * pp], aL[kk], bH[0], bH[1]);
                mma16816(acc2[2 * pp + 1], aH[kk], bH[2], bH[3]);
                mma16816(acc2[2 * pp + 1], aH[kk], bL[2], bL[3]);
                mma16816(acc2[2 * pp + 1], aL[kk], bH[2], bH[3]);
            }
        }
        // write partner's n-half partials to ZP
        #pragma unroll
        for (int q = 0; q < 4; q++) {
            int nb2 = (1 - nhf) * 4 + q;
            int n = nb2 * 8 + 2 * t;
            float2 vA; vA.x = acc2[nb2][0]; vA.y = acc2[nb2][1];
            float2 vB; vB.x = acc2[nb2][2]; vB.y = acc2[nb2][3];
            *(float2*)&s_zp[rA * ZP_STRIDE + n] = vA;
            *(float2*)&s_zp[rB * ZP_STRIDE + n] = vB;
        }
        asm volatile("bar.sync %0, 64;" :: "r"(rbw + 1) : "memory");   // pair barrier

        // -------- P2b: combine partials, bias, ||z||^2, split -> ZB --------
        {
            float z2A = 0.f, z2B = 0.f;
            #pragma unroll
            for (int q = 0; q < 4; q++) {
                int nb2 = nhf * 4 + q;
                int n = nb2 * 8 + 2 * t;
                int w = n >> 1;
                float2 pA = *(float2*)&s_zp[rA * ZP_STRIDE + n];
                float2 pB = *(float2*)&s_zp[rB * ZP_STRIDE + n];
                float bb0 = s_b2[n], bb1 = s_b2[n + 1];
                float z00 = acc2[nb2][0] + pA.x + bb0;
                float z01 = acc2[nb2][1] + pA.y + bb1;
                float z10 = acc2[nb2][2] + pB.x + bb0;
                float z11 = acc2[nb2][3] + pB.y + bb1;
                z2A = fmaf(z00, z00, fmaf(z01, z01, z2A));
                z2B = fmaf(z10, z10, fmaf(z11, z11, z2B));
                uint32_t lo;
                uint32_t hi = pack2_split_hi(z00, z01, lo);
                *(uint32_t*)(smem + OF_ZBH + SWZ_W(rA, w)) = hi;
                *(uint32_t*)(smem + OF_ZBL + SWZ_W(rA, w)) = lo;
                hi = pack2_split_hi(z10, z11, lo);
                *(uint32_t*)(smem + OF_ZBH + SWZ_W(rB, w)) = hi;
                *(uint32_t*)(smem + OF_ZBL + SWZ_W(rB, w)) = lo;
            }
            #pragma unroll
            for (int off = 1; off <= 2; off <<= 1) {
                z2A += __shfl_xor_sync(0xffffffffu, z2A, off);
                z2B += __shfl_xor_sync(0xffffffffu, z2B, off);
            }
            if (t == 0) {
                s_z2[rA * 2 + nhf] = z2A;
                s_z2[rB * 2 + nhf] = z2B;
            }
        }
        __syncthreads();   // C

        // -------- P3: distance MMA over row-blocks; warp owns 32 codes --------
        #pragma unroll 1
        for (int rb = 0; rb < 8; rb++) {
            const int R0 = rb * 16;
            const int a_row3 = R0 + a_roff;
            uint32_t afH[4][4], afL[4][4];
            #pragma unroll
            for (int kk = 0; kk < 4; kk++) {
                uint32_t off = SWZ_C(a_row3, 2 * kk + a_ch);
                ldsm_x4(afH[kk], smb + OF_ZBH + off);
                ldsm_x4(afL[kk], smb + OF_ZBL + off);
            }
            float acc3[4][4];
            #pragma unroll
            for (int nb = 0; nb < 4; nb++)
                #pragma unroll
                for (int u = 0; u < 4; u++) acc3[nb][u] = 0.f;

            #pragma unroll
            for (int kk = 0; kk < 4; kk++) {
                #pragma unroll
                for (int pp = 0; pp < 2; pp++) {
                    uint32_t bL[4];
                    ldsm_x4(bL, smb + OF_CBL + SWZ_C(warp * 32 + pp * 16 + b_row0, 2 * kk + b_ch));
                    mma16816(acc3[2 * pp],     afH[kk], bL[0], bL[1]);   // zH*eL
                    mma16816(acc3[2 * pp + 1], afH[kk], bL[2], bL[3]);
                }
                #pragma unroll
                for (int nb = 0; nb < 4; nb++) {
                    mma16816(acc3[nb], afH[kk], bregH[nb][kk][0], bregH[nb][kk][1]);  // zH*eH
                    mma16816(acc3[nb], afL[kk], bregH[nb][kk][0], bregH[nb][kk][1]);  // zL*eH
                }
            }
            float mA = 3.4e38f, mB = 3.4e38f; int iA = 0, iB = 0;
            #pragma unroll
            for (int nb = 0; nb < 4; nb++) {
                int c0 = warp * 32 + nb * 8 + 2 * t;
                float e0 = s_e2[c0], e1 = s_e2[c0 + 1];
                float d00 = fmaf(-2.f, acc3[nb][0], e0);
                float d01 = fmaf(-2.f, acc3[nb][1], e1);
                float d10 = fmaf(-2.f, acc3[nb][2], e0);
                float d11 = fmaf(-2.f, acc3[nb][3], e1);
                if (d00 < mA) { mA = d00; iA = c0; }
                if (d01 < mA) { mA = d01; iA = c0 + 1; }
                if (d10 < mB) { mB = d10; iB = c0; }
                if (d11 < mB) { mB = d11; iB = c0 + 1; }
            }
            #pragma unroll
            for (int off = 1; off <= 2; off <<= 1) {
                float ov = __shfl_xor_sync(0xffffffffu, mA, off);
                int   oi = __shfl_xor_sync(0xffffffffu, iA, off);
                if (ov < mA || (ov == mA && oi < iA)) { mA = ov; iA = oi; }
                ov = __shfl_xor_sync(0xffffffffu, mB, off);
                oi = __shfl_xor_sync(0xffffffffu, iB, off);
                if (ov < mB || (ov == mB && oi < iB)) { mB = ov; iB = oi; }
            }
            if (t == 0) {
                atomicMin(&s_cand[R0 + g], dist_key(mA, iA));
                atomicMin(&s_cand[R0 + 8 + g], dist_key(mB, iB));
            }
        }
        __syncthreads();   // D

        // -------- P4: idx + vq = d_min + ||z||^2; reset cand --------
        if (tid < TILE_M) {
            unsigned long long key = s_cand[tid];
            g_idx[tle * TILE_M + tid] = (int)(key & 0xFFFFFFFFu);
            s_cand[tid] = ~0ULL;
            vq_local += dist_unkey(key) + s_z2[2 * tid] + s_z2[2 * tid + 1];
        }
        // no barrier: next P0 writes only XB; cand/z2 rewrites are post-A/C
    }

    // ---- reduce vq ----
    #pragma unroll
    for (int off = 16; off; off >>= 1) vq_local += __shfl_down_sync(0xffffffffu, vq_local, off);
    __syncthreads();
    float* s_red = (float*)(smem + OF_ZP);
    if (lane == 0) s_red[warp] = vq_local;
    __syncthreads();
    if (tid == 0) {
        float s = 0.f;
        for (int w = 0; w < EWARPS; w++) s += s_red[w];
        g_vq_part[blockIdx.x] = s;
    }
}

// ============================================================================
// decoder table for 512 codes (exact fp32)
// ============================================================================
__global__ void k_hd(const float* __restrict__ cb,
                     const float* __restrict__ dw1, const float* __restrict__ db1)
{
    int gid = blockIdx.x * blockDim.x + threadIdx.x;
    int c = gid >> 7, j = gid & 127;
    float acc = db1[j];
    const float* q = cb + c * LAT;
    #pragma unroll 8
    for (int k = 0; k < LAT; k++) acc = fmaf(q[k], dw1[k * HID + j], acc);
    g_hd[gid] = fmaxf(acc, 0.f);
}

__global__ void k_tbl(const float* __restrict__ dw2, const float* __restrict__ db2)
{
    int gid = blockIdx.x * blockDim.x + threadIdx.x;
    int c = gid / IN_DIM, j = gid - c * IN_DIM;
    float acc = db2[j];
    const float* hd = g_hd + c * HID;
    #pragma unroll 8
    for (int k = 0; k < HID; k++) acc = fmaf(hd[k], dw2[k * IN_DIM + j], acc);
    g_tbl[gid] = acc;
}

// ============================================================================
// k_out: gather recon from table, write out, recon-loss partials
// ============================================================================
#define OUT_THREADS 512
__global__ void __launch_bounds__(OUT_THREADS)
k_out(const float* __restrict__ x, float* __restrict__ out)
{
    const int total4 = B_TOTAL * (IN_DIM / 4);          // 7 float4 per row
    const float4* x4 = (const float4*)x;
    float4* o4 = (float4*)out;
    const float4* t4 = (const float4*)g_tbl;

    float rec = 0.f;
    for (int f4 = blockIdx.x * OUT_THREADS + threadIdx.x; f4 < total4;
         f4 += KOUT_GRID * OUT_THREADS) {
        int row = f4 / 7;
        int w = f4 - row * 7;
        int idx = g_idx[row];
        float4 tv = t4[idx * 7 + w];
        float4 xv = x4[f4];
        o4[f4] = tv;
        float d0 = tv.x - xv.x, d1 = tv.y - xv.y, d2 = tv.z - xv.z, d3 = tv.w - xv.w;
        rec = fmaf(d0, d0, fmaf(d1, d1, fmaf(d2, d2, fmaf(d3, d3, rec))));
    }
    __shared__ float s_red[OUT_THREADS / 32];
    #pragma unroll
    for (int off = 16; off; off >>= 1) rec += __shfl_down_sync(0xffffffffu, rec, off);
    if ((threadIdx.x & 31) == 0) s_red[threadIdx.x >> 5] = rec;
    __syncthreads();
    if (threadIdx.x == 0) {
        float s = 0.f;
        for (int w = 0; w < OUT_THREADS / 32; w++) s += s_red[w];
        g_rec_part[blockIdx.x] = s;
    }
}

// ============================================================================
// finalize scalar losses
// ============================================================================
__global__ void k_final(float* __restrict__ out)
{
    if (threadIdx.x == 0) {
        double vs = 0.0, rs = 0.0;
        for (int i = 0; i < GRID1; i++) vs += (double)g_vq_part[i];
        for (int i = 0; i < KOUT_GRID; i++) rs += (double)g_rec_part[i];
        out[(long)B_TOTAL * IN_DIM]     = (float)(rs / ((double)B_TOTAL * IN_DIM));
        out[(long)B_TOTAL * IN_DIM + 1] = (float)(1.25 * vs / ((double)B_TOTAL * LAT));
    }
}

// ============================================================================
extern "C" void kernel_launch(void* const* d_in, const int* in_sizes, int n_in,
                              void* d_out, int out_size)
{
    const float* x    = (const float*)d_in[0];
    const float* ew1  = (const float*)d_in[1];
    const float* eb1  = (const float*)d_in[2];
    const float* ew2  = (const float*)d_in[3];
    const float* eb2  = (const float*)d_in[4];
    const float* cb   = (const float*)d_in[5];
    const float* dw1  = (const float*)d_in[6];
    const float* db1  = (const float*)d_in[7];
    const float* dw2  = (const float*)d_in[8];
    const float* db2  = (const float*)d_in[9];
    float* out = (float*)d_out;

    cudaFuncSetAttribute(k_encode, cudaFuncAttributeMaxDynamicSharedMemorySize, SMEM_E);

    k_hd<<<(NCODES * HID) / 256, 256>>>(cb, dw1, db1);
    k_tbl<<<(NCODES * IN_DIM) / 256, 256>>>(dw2, db2);
    k_encode<<<GRID1, ETHREADS, SMEM_E>>>(x, ew1, eb1, ew2, eb2, cb);
    k_out<<<KOUT_GRID, OUT_THREADS>>>(x, out);
    k_final<<<1, 32>>>(out);
}

// round 10
// speedup vs baseline: 1.1332x; 1.1332x over previous
#include <cuda_runtime.h>
#include <cuda_bf16.h>
#include <cstdint>

#define B_TOTAL 262144
#define IN_DIM 28
#define HID 128
#define LAT 64
#define NCODES 512
#define GRID1 148
#define TILE_M 128
#define NTILES (B_TOTAL / TILE_M)   // 2048

#define ETHREADS 512
#define EWARPS 16

// ---- k_encode smem layout (bytes) ----
#define OF_CBL   0                      // codebook lo bf16, 512x128B = 65536
#define OF_HT    65536                  // h tiles HH0,HH1,HL0,HL1 (16K each); CBH staging at init
#define OF_ZBH   131072                 // z hi 128x128B (aliased: XBH during stage-x/P1)
#define OF_ZBL   147456                 // z lo
#define OF_XBH   OF_ZBH
#define OF_XBL   OF_ZBL
#define OF_W2    163840                 // W2H0,W2H1,W2L0,W2L1 (8K each) = 32768
#define OF_W1TH  196608                 // W1^T hi [128n][32k] 64B rows = 8192
#define OF_W1TL  204800                 // 8192
#define OF_B1    212992                 // 512
#define OF_B2    213504                 // 256
#define OF_E2    213760                 // 2048
#define OF_CD    215808                 // float[128][17] = 8704
#define OF_CI    224512                 // u16[128][17]   = 4352
#define SMEM_E   228864

// XOR swizzle, 128B rows (16B granularity)
#define SWZ_W(row, w)  ((row) * 128 + ((((w) >> 2) ^ ((row) & 7)) << 4) + ((w) & 3) * 4)
#define SWZ_C(row, ch) ((row) * 128 + ((((ch)) ^ ((row) & 7)) << 4))
// XOR swizzle, 64B rows
#define SWZ64_W(row, w)  ((row) * 64 + ((((w) >> 2) ^ (((row) >> 1) & 3)) << 4) + ((w) & 3) * 4)
#define SWZ64_C(row, ch) ((row) * 64 + ((((ch)) ^ (((row) >> 1) & 3)) << 4))

#define KOUT_GRID 592

__device__ int    g_idx[B_TOTAL];
__device__ float  g_vq_part[GRID1];
__device__ float  g_rec_part[KOUT_GRID];
__device__ float  g_hd[NCODES * HID];
__device__ float  g_tbl[NCODES * IN_DIM];

// ---------------- helpers ----------------
__device__ __forceinline__ uint32_t smem_u32_of(const void* p) {
    uint32_t a;
    asm("{ .reg .u64 t; cvta.to.shared.u64 t, %1; cvt.u32.u64 %0, t; }" : "=r"(a) : "l"(p));
    return a;
}
__device__ __forceinline__ void ldsm_x4(uint32_t* r, uint32_t addr) {
    asm volatile("ldmatrix.sync.aligned.m8n8.x4.shared.b16 {%0,%1,%2,%3}, [%4];"
        : "=r"(r[0]), "=r"(r[1]), "=r"(r[2]), "=r"(r[3]) : "r"(addr));
}
__device__ __forceinline__ void mma16816(float* d, const uint32_t* a, uint32_t b0, uint32_t b1) {
    asm volatile("mma.sync.aligned.m16n8k16.row.col.f32.bf16.bf16.f32 "
        "{%0,%1,%2,%3}, {%4,%5,%6,%7}, {%8,%9}, {%0,%1,%2,%3};"
        : "+f"(d[0]), "+f"(d[1]), "+f"(d[2]), "+f"(d[3])
        : "r"(a[0]), "r"(a[1]), "r"(a[2]), "r"(a[3]), "r"(b0), "r"(b1));
}
__device__ __forceinline__ void bf16_split(float v, __nv_bfloat16& hi, __nv_bfloat16& lo) {
    hi = __float2bfloat16(v);
    lo = __float2bfloat16(v - __bfloat162float(hi));
}
__device__ __forceinline__ uint32_t pack2_split_hi(float a, float b, uint32_t& lo_out) {
    __nv_bfloat16 ha, la, hb, lb;
    bf16_split(a, ha, la); bf16_split(b, hb, lb);
    __nv_bfloat162 ph; ph.x = ha; ph.y = hb;
    __nv_bfloat162 pl; pl.x = la; pl.y = lb;
    lo_out = *(uint32_t*)&pl;
    return *(uint32_t*)&ph;
}

// ============================================================================
// K1: encoder — MMA enc1, MMA enc2, distance MMA w/ reg-resident CBH,
//     slot-based argmin combine, prefetched x
// ============================================================================
__global__ void __launch_bounds__(ETHREADS, 1)
k_encode(const float* __restrict__ x,
         const float* __restrict__ w1, const float* __restrict__ b1,
         const float* __restrict__ w2, const float* __restrict__ b2,
         const float* __restrict__ cb)
{
    extern __shared__ char smem[];
    const uint32_t smb = smem_u32_of(smem);

    float* s_b1 = (float*)(smem + OF_B1);
    float* s_b2 = (float*)(smem + OF_B2);
    float* s_e2 = (float*)(smem + OF_E2);
    float* s_cd = (float*)(smem + OF_CD);
    unsigned short* s_ci = (unsigned short*)(smem + OF_CI);

    const int tid = threadIdx.x;
    const int warp = tid >> 5, lane = tid & 31;

    // ---- prefetch first tile's x into registers (overlaps init) ----
    float4 xr0, xr1;
    {
        const float4* xg4 = (const float4*)(x + (long)blockIdx.x * TILE_M * IN_DIM);
        xr0 = xg4[tid];
        if (tid < TILE_M * 7 - ETHREADS) xr1 = xg4[tid + ETHREADS];
    }

    // ---- init ----
    for (int i = tid; i < HID; i += ETHREADS) s_b1[i] = b1[i];
    for (int i = tid; i < LAT; i += ETHREADS) s_b2[i] = b2[i];
    // codebook split: hi -> HT staging, lo -> CBL (128B rows)
    for (int i = tid; i < NCODES * 32; i += ETHREADS) {
        int c = i >> 5, w = i & 31;
        uint32_t lo;
        uint32_t hi = pack2_split_hi(cb[c * LAT + 2 * w], cb[c * LAT + 2 * w + 1], lo);
        *(uint32_t*)(smem + OF_HT  + SWZ_W(c, w)) = hi;   // staging
        *(uint32_t*)(smem + OF_CBL + SWZ_W(c, w)) = lo;
    }
    // W2^T split: [64 n][128 k] as two k-halves, 128B rows
    for (int i = tid; i < LAT * 64; i += ETHREADS) {
        int n = i >> 6, kw = i & 63;
        uint32_t lo;
        uint32_t hi = pack2_split_hi(w2[2 * kw * LAT + n], w2[(2 * kw + 1) * LAT + n], lo);
        int khalf = kw >> 5, w = kw & 31;
        *(uint32_t*)(smem + OF_W2 + khalf * 8192 + SWZ_W(n, w))         = hi;
        *(uint32_t*)(smem + OF_W2 + 16384 + khalf * 8192 + SWZ_W(n, w)) = lo;
    }
    // W1^T split: [128 n][32 k], 64B rows; zero-pad k 28..31
    for (int i = tid; i < HID * 14; i += ETHREADS) {
        int n = i / 14, kw = i - n * 14;
        uint32_t lo;
        uint32_t hi = pack2_split_hi(w1[2 * kw * HID + n], w1[(2 * kw + 1) * HID + n], lo);
        *(uint32_t*)(smem + OF_W1TH + SWZ64_W(n, kw)) = hi;
        *(uint32_t*)(smem + OF_W1TL + SWZ64_W(n, kw)) = lo;
    }
    for (int i = tid; i < HID * 2; i += ETHREADS) {
        int n = i >> 1, w = 14 + (i & 1);
        *(uint32_t*)(smem + OF_W1TH + SWZ64_W(n, w)) = 0;
        *(uint32_t*)(smem + OF_W1TL + SWZ64_W(n, w)) = 0;
    }
    // XB k-pad (words 14,15): static garbage-guard (W1T rows there are zero)
    for (int i = tid; i < TILE_M * 2; i += ETHREADS) {
        int row = i >> 1, w = 14 + (i & 1);
        *(uint32_t*)(smem + OF_XBH + SWZ64_W(row, w)) = 0;
        *(uint32_t*)(smem + OF_XBL + SWZ64_W(row, w)) = 0;
    }
    for (int c = tid; c < NCODES; c += ETHREADS) {
        float s = 0.f;
        for (int k = 0; k < LAT; k++) { float v = cb[c * LAT + k]; s = fmaf(v, v, s); }
        s_e2[c] = s;
    }
    __syncthreads();

    // mma lane-role constants
    const int g = lane >> 2, t = lane & 3;
    const int a_roff = (lane & 7) + 8 * ((lane >> 3) & 1);
    const int a_ch   = lane >> 4;
    const int b_row0 = (lane & 7) + 8 * ((lane >> 4) & 1);
    const int b_ch   = (lane >> 3) & 1;

    // ---- this warp's CBH fragments -> registers (from staging) ----
    uint32_t bregH[4][4][2];
    #pragma unroll
    for (int pp = 0; pp < 2; pp++)
        #pragma unroll
        for (int kk = 0; kk < 4; kk++) {
            uint32_t r4[4];
            ldsm_x4(r4, smb + OF_HT + SWZ_C(warp * 32 + pp * 16 + b_row0, 2 * kk + b_ch));
            bregH[2 * pp][kk][0] = r4[0];     bregH[2 * pp][kk][1] = r4[1];
            bregH[2 * pp + 1][kk][0] = r4[2]; bregH[2 * pp + 1][kk][1] = r4[3];
        }
    __syncthreads();   // HT staging now free

    const int rbw = warp >> 1, nhf = warp & 1;
    const int R0w = rbw * 16;
    const int rA = R0w + g, rB = rA + 8;
    float vq_local = 0.f;

    for (int tle = blockIdx.x; tle < NTILES; tle += GRID1) {
        // -------- P0: store prefetched x regs into XB hi/lo (no load wait) --------
        {
            int row = tid / 7, w4 = tid - row * 7;
            uint32_t lo0, lo1;
            uint32_t hi0 = pack2_split_hi(xr0.x, xr0.y, lo0);
            uint32_t hi1 = pack2_split_hi(xr0.z, xr0.w, lo1);
            *(uint64_t*)(smem + OF_XBH + SWZ64_W(row, 2 * w4)) =
                (uint64_t)hi0 | ((uint64_t)hi1 << 32);
            *(uint64_t*)(smem + OF_XBL + SWZ64_W(row, 2 * w4)) =
                (uint64_t)lo0 | ((uint64_t)lo1 << 32);
            if (tid < TILE_M * 7 - ETHREADS) {
                int i2 = tid + ETHREADS;
                int row2 = i2 / 7, w42 = i2 - row2 * 7;
                uint32_t hi2 = pack2_split_hi(xr1.x, xr1.y, lo0);
                uint32_t hi3 = pack2_split_hi(xr1.z, xr1.w, lo1);
                *(uint64_t*)(smem + OF_XBH + SWZ64_W(row2, 2 * w42)) =
                    (uint64_t)hi2 | ((uint64_t)hi3 << 32);
                *(uint64_t*)(smem + OF_XBL + SWZ64_W(row2, 2 * w42)) =
                    (uint64_t)lo0 | ((uint64_t)lo1 << 32);
            }
        }
        __syncthreads();   // A

        // issue global loads for next tile (hidden behind P1-P3 compute)
        {
            int nt = tle + GRID1;
            if (nt < NTILES) {
                const float4* xg4 = (const float4*)(x + (long)nt * TILE_M * IN_DIM);
                xr0 = xg4[tid];
                if (tid < TILE_M * 7 - ETHREADS) xr1 = xg4[tid + ETHREADS];
            }
        }

        // -------- P1: enc1 MMA: h = relu(x @ W1 + b1) -> HT tiles --------
        {
            float acc[8][4];
            #pragma unroll
            for (int nb = 0; nb < 8; nb++)
                #pragma unroll
                for (int u = 0; u < 4; u++) acc[nb][u] = 0.f;

            #pragma unroll
            for (int kk = 0; kk < 2; kk++) {
                uint32_t xH[4], xL[4];
                uint32_t offA = SWZ64_C(R0w + a_roff, 2 * kk + a_ch);
                ldsm_x4(xH, smb + OF_XBH + offA);
                ldsm_x4(xL, smb + OF_XBL + offA);
                #pragma unroll
                for (int pp = 0; pp < 4; pp++) {
                    int nrow = nhf * 64 + pp * 16 + b_row0;
                    uint32_t offB = SWZ64_C(nrow, 2 * kk + b_ch);
                    uint32_t bH[4], bL[4];
                    ldsm_x4(bH, smb + OF_W1TH + offB);
                    ldsm_x4(bL, smb + OF_W1TL + offB);
                    mma16816(acc[2 * pp], xH, bH[0], bH[1]);
                    mma16816(acc[2 * pp], xH, bL[0], bL[1]);
                    mma16816(acc[2 * pp], xL, bH[0], bH[1]);
                    mma16816(acc[2 * pp + 1], xH, bH[2], bH[3]);
                    mma16816(acc[2 * pp + 1], xH, bL[2], bL[3]);
                    mma16816(acc[2 * pp + 1], xL, bH[2], bH[3]);
                }
            }
            #pragma unroll
            for (int nb = 0; nb < 8; nb++) {
                int c = nhf * 64 + nb * 8 + 2 * t;
                float bb0 = s_b1[c], bb1 = s_b1[c + 1];
                int w = nb * 4 + t;
                float h00 = fmaxf(acc[nb][0] + bb0, 0.f);
                float h01 = fmaxf(acc[nb][1] + bb1, 0.f);
                float h10 = fmaxf(acc[nb][2] + bb0, 0.f);
                float h11 = fmaxf(acc[nb][3] + bb1, 0.f);
                uint32_t lo;
                uint32_t hi = pack2_split_hi(h00, h01, lo);
                *(uint32_t*)(smem + OF_HT + nhf * 16384 + SWZ_W(rA, w)) = hi;
                *(uint32_t*)(smem + OF_HT + 32768 + nhf * 16384 + SWZ_W(rA, w)) = lo;
                hi = pack2_split_hi(h10, h11, lo);
                *(uint32_t*)(smem + OF_HT + nhf * 16384 + SWZ_W(rB, w)) = hi;
                *(uint32_t*)(smem + OF_HT + 32768 + nhf * 16384 + SWZ_W(rB, w)) = lo;
            }
        }
        __syncthreads();   // B

        // -------- P2: enc2 MMA: z = h @ W2 + b2 -> ZB; fold ||z||^2 into vq --------
        {
            const int a_row2 = R0w + a_roff;
            float acc2[4][4];
            #pragma unroll
            for (int nb = 0; nb < 4; nb++)
                #pragma unroll
                for (int u = 0; u < 4; u++) acc2[nb][u] = 0.f;

            #pragma unroll
            for (int khalf = 0; khalf < 2; khalf++) {
                #pragma unroll
                for (int kk = 0; kk < 4; kk++) {
                    uint32_t aH[4], aL[4];
                    uint32_t offA = SWZ_C(a_row2, 2 * kk + a_ch);
                    ldsm_x4(aH, smb + OF_HT + khalf * 16384 + offA);
                    ldsm_x4(aL, smb + OF_HT + 32768 + khalf * 16384 + offA);
                    #pragma unroll
                    for (int pp = 0; pp < 2; pp++) {
                        int nrow = nhf * 32 + pp * 16 + b_row0;
                        uint32_t offB = SWZ_C(nrow, 2 * kk + b_ch);
                        uint32_t bH[4], bL[4];
                        ldsm_x4(bH, smb + OF_W2 + khalf * 8192 + offB);
                        ldsm_x4(bL, smb + OF_W2 + 16384 + khalf * 8192 + offB);
                        mma16816(acc2[2 * pp], aH, bH[0], bH[1]);
                        mma16816(acc2[2 * pp], aH, bL[0], bL[1]);
                        mma16816(acc2[2 * pp], aL, bH[0], bH[1]);
                        mma16816(acc2[2 * pp + 1], aH, bH[2], bH[3]);
                        mma16816(acc2[2 * pp + 1], aH, bL[2], bL[3]);
                        mma16816(acc2[2 * pp + 1], aL, bH[2], bH[3]);
                    }
                }
            }
            float z2sum = 0.f;
            #pragma unroll
            for (int nb = 0; nb < 4; nb++) {
                int c0 = nhf * 32 + nb * 8 + 2 * t;
                int w = c0 >> 1;
                float bb0 = s_b2[c0], bb1 = s_b2[c0 + 1];
                float z00 = acc2[nb][0] + bb0, z01 = acc2[nb][1] + bb1;
                float z10 = acc2[nb][2] + bb0, z11 = acc2[nb][3] + bb1;
                z2sum = fmaf(z00, z00, fmaf(z01, z01, z2sum));
                z2sum = fmaf(z10, z10, fmaf(z11, z11, z2sum));
                uint32_t lo;
                uint32_t hi = pack2_split_hi(z00, z01, lo);
                *(uint32_t*)(smem + OF_ZBH + SWZ_W(rA, w)) = hi;
                *(uint32_t*)(smem + OF_ZBL + SWZ_W(rA, w)) = lo;
                hi = pack2_split_hi(z10, z11, lo);
                *(uint32_t*)(smem + OF_ZBH + SWZ_W(rB, w)) = hi;
                *(uint32_t*)(smem + OF_ZBL + SWZ_W(rB, w)) = lo;
            }
            vq_local += z2sum;    // sums over lanes/warps give total ||z||^2
        }
        __syncthreads();   // C

        // -------- P3: distance MMA over row-blocks; warp owns 32 codes --------
        #pragma unroll 1
        for (int rb = 0; rb < 8; rb++) {
            const int R0 = rb * 16;
            const int a_row3 = R0 + a_roff;
            uint32_t afH[4][4], afL[4][4];
            #pragma unroll
            for (int kk = 0; kk < 4; kk++) {
                uint32_t off = SWZ_C(a_row3, 2 * kk + a_ch);
                ldsm_x4(afH[kk], smb + OF_ZBH + off);
                ldsm_x4(afL[kk], smb + OF_ZBL + off);
            }
            float acc3[4][4];
            #pragma unroll
            for (int nb = 0; nb < 4; nb++)
                #pragma unroll
                for (int u = 0; u < 4; u++) acc3[nb][u] = 0.f;

            #pragma unroll
            for (int kk = 0; kk < 4; kk++) {
                #pragma unroll
                for (int pp = 0; pp < 2; pp++) {
                    uint32_t bL[4];
                    ldsm_x4(bL, smb + OF_CBL + SWZ_C(warp * 32 + pp * 16 + b_row0, 2 * kk + b_ch));
                    mma16816(acc3[2 * pp],     afH[kk], bL[0], bL[1]);   // zH*eL
                    mma16816(acc3[2 * pp + 1], afH[kk], bL[2], bL[3]);
                }
                #pragma unroll
                for (int nb = 0; nb < 4; nb++) {
                    mma16816(acc3[nb], afH[kk], bregH[nb][kk][0], bregH[nb][kk][1]);  // zH*eH
                    mma16816(acc3[nb], afL[kk], bregH[nb][kk][0], bregH[nb][kk][1]);  // zL*eH
                }
            }
            float mA = 3.4e38f, mB = 3.4e38f; int iA = 0, iB = 0;
            #pragma unroll
            for (int nb = 0; nb < 4; nb++) {
                int c0 = warp * 32 + nb * 8 + 2 * t;
                float e0 = s_e2[c0], e1 = s_e2[c0 + 1];
                float d00 = fmaf(-2.f, acc3[nb][0], e0);
                float d01 = fmaf(-2.f, acc3[nb][1], e1);
                float d10 = fmaf(-2.f, acc3[nb][2], e0);
                float d11 = fmaf(-2.f, acc3[nb][3], e1);
                if (d00 < mA) { mA = d00; iA = c0; }
                if (d01 < mA) { mA = d01; iA = c0 + 1; }
                if (d10 < mB) { mB = d10; iB = c0; }
                if (d11 < mB) { mB = d11; iB = c0 + 1; }
            }
            #pragma unroll
            for (int off = 1; off <= 2; off <<= 1) {
                float ov = __shfl_xor_sync(0xffffffffu, mA, off);
                int   oi = __shfl_xor_sync(0xffffffffu, iA, off);
                if (ov < mA || (ov == mA && oi < iA)) { mA = ov; iA = oi; }
                ov = __shfl_xor_sync(0xffffffffu, mB, off);
                oi = __shfl_xor_sync(0xffffffffu, iB, off);
                if (ov < mB || (ov == mB && oi < iB)) { mB = ov; iB = oi; }
            }
            if (t == 0) {   // one unique slot per (row, warp): no atomics needed
                s_cd[(R0 + g) * 17 + warp]     = mA;
                s_ci[(R0 + g) * 17 + warp]     = (unsigned short)iA;
                s_cd[(R0 + 8 + g) * 17 + warp] = mB;
                s_ci[(R0 + 8 + g) * 17 + warp] = (unsigned short)iB;
            }
        }
        __syncthreads();   // D

        // -------- P4: per-row scan of 16 warp-candidates; vq += d_min --------
        if (tid < TILE_M) {
            const float* rowd = s_cd + tid * 17;
            const unsigned short* rowi = s_ci + tid * 17;
            float best = rowd[0];
            int   bi   = rowi[0];
            #pragma unroll
            for (int w = 1; w < EWARPS; w++) {
                float dw = rowd[w];
                if (dw < best) { best = dw; bi = rowi[w]; }  // ties -> lower warp = lower code
            }
            g_idx[tle * TILE_M + tid] = bi;
            vq_local += best;
        }
        // no barrier: next P0 writes only XB(=ZB), dead since D; CD/CI rewritten after next C
    }

    // ---- reduce vq ----
    #pragma unroll
    for (int off = 16; off; off >>= 1) vq_local += __shfl_down_sync(0xffffffffu, vq_local, off);
    __syncthreads();
    float* s_red = (float*)(smem + OF_CD);
    if (lane == 0) s_red[warp] = vq_local;
    __syncthreads();
    if (tid == 0) {
        float s = 0.f;
        for (int w = 0; w < EWARPS; w++) s += s_red[w];
        g_vq_part[blockIdx.x] = s;
    }
}

// ============================================================================
// decoder table for 512 codes (exact fp32)
// ============================================================================
__global__ void k_hd(const float* __restrict__ cb,
                     const float* __restrict__ dw1, const float* __restrict__ db1)
{
    int gid = blockIdx.x * blockDim.x + threadIdx.x;
    int c = gid >> 7, j = gid & 127;
    float acc = db1[j];
    const float* q = cb + c * LAT;
    #pragma unroll 8
    for (int k = 0; k < LAT; k++) acc = fmaf(q[k], dw1[k * HID + j], acc);
    g_hd[gid] = fmaxf(acc, 0.f);
}

__global__ void k_tbl(const float* __restrict__ dw2, const float* __restrict__ db2)
{
    int gid = blockIdx.x * blockDim.x + threadIdx.x;
    int c = gid / IN_DIM, j = gid - c * IN_DIM;
    float acc = db2[j];
    const float* hd = g_hd + c * HID;
    #pragma unroll 8
    for (int k = 0; k < HID; k++) acc = fmaf(hd[k], dw2[k * IN_DIM + j], acc);
    g_tbl[gid] = acc;
}

// ============================================================================
// k_out: gather recon from table, write out, recon-loss partials
// ============================================================================
#define OUT_THREADS 512
__global__ void __launch_bounds__(OUT_THREADS)
k_out(const float* __restrict__ x, float* __restrict__ out)
{
    const int total4 = B_TOTAL * (IN_DIM / 4);          // 7 float4 per row
    const float4* x4 = (const float4*)x;
    float4* o4 = (float4*)out;
    const float4* t4 = (const float4*)g_tbl;

    float rec = 0.f;
    for (int f4 = blockIdx.x * OUT_THREADS + threadIdx.x; f4 < total4;
         f4 += KOUT_GRID * OUT_THREADS) {
        int row = f4 / 7;
        int w = f4 - row * 7;
        int idx = g_idx[row];
        float4 tv = t4[idx * 7 + w];
        float4 xv = x4[f4];
        o4[f4] = tv;
        float d0 = tv.x - xv.x, d1 = tv.y - xv.y, d2 = tv.z - xv.z, d3 = tv.w - xv.w;
        rec = fmaf(d0, d0, fmaf(d1, d1, fmaf(d2, d2, fmaf(d3, d3, rec))));
    }
    __shared__ float s_red[OUT_THREADS / 32];
    #pragma unroll
    for (int off = 16; off; off >>= 1) rec += __shfl_down_sync(0xffffffffu, rec, off);
    if ((threadIdx.x & 31) == 0) s_red[threadIdx.x >> 5] = rec;
    __syncthreads();
    if (threadIdx.x == 0) {
        float s = 0.f;
        for (int w = 0; w < OUT_THREADS / 32; w++) s += s_red[w];
        g_rec_part[blockIdx.x] = s;
    }
}

// ============================================================================
// finalize scalar losses
// ============================================================================
__global__ void k_final(float* __restrict__ out)
{
    if (threadIdx.x == 0) {
        double vs = 0.0, rs = 0.0;
        for (int i = 0; i < GRID1; i++) vs += (double)g_vq_part[i];
        for (int i = 0; i < KOUT_GRID; i++) rs += (double)g_rec_part[i];
        out[(long)B_TOTAL * IN_DIM]     = (float)(rs / ((double)B_TOTAL * IN_DIM));
        out[(long)B_TOTAL * IN_DIM + 1] = (float)(1.25 * vs / ((double)B_TOTAL * LAT));
    }
}

// ============================================================================
extern "C" void kernel_launch(void* const* d_in, const int* in_sizes, int n_in,
                              void* d_out, int out_size)
{
    const float* x    = (const float*)d_in[0];
    const float* ew1  = (const float*)d_in[1];
    const float* eb1  = (const float*)d_in[2];
    const float* ew2  = (const float*)d_in[3];
    const float* eb2  = (const float*)d_in[4];
    const float* cb   = (const float*)d_in[5];
    const float* dw1  = (const float*)d_in[6];
    const float* db1  = (const float*)d_in[7];
    const float* dw2  = (const float*)d_in[8];
    const float* db2  = (const float*)d_in[9];
    float* out = (float*)d_out;

    cudaFuncSetAttribute(k_encode, cudaFuncAttributeMaxDynamicSharedMemorySize, SMEM_E);

    k_hd<<<(NCODES * HID) / 256, 256>>>(cb, dw1, db1);
    k_tbl<<<(NCODES * IN_DIM) / 256, 256>>>(dw2, db2);
    k_encode<<<GRID1, ETHREADS, SMEM_E>>>(x, ew1, eb1, ew2, eb2, cb);
    k_out<<<KOUT_GRID, OUT_THREADS>>>(x, out);
    k_final<<<1, 32>>>(out);
}

// round 11
// speedup vs baseline: 1.2017x; 1.0604x over previous
#include <cuda_runtime.h>
#include <cuda_bf16.h>
#include <cstdint>

#define B_TOTAL 262144
#define IN_DIM 28
#define HID 128
#define LAT 64
#define NCODES 512
#define GRID1 148
#define TILE_M 128
#define NTILES (B_TOTAL / TILE_M)   // 2048

#define ETHREADS 512
#define EWARPS 16

// ---- k_encode smem layout (bytes) ----
#define OF_HT    0                      // 65536: h tiles HH0,HH1,HL0,HL1; CBH/CBL staging at init
#define OF_ZBH   65536                  // z hi 128x128B (alias XBH)
#define OF_ZBL   81920                  // z lo (alias XBL)
#define OF_XBH   OF_ZBH
#define OF_XBL   OF_ZBL
#define OF_W2    98304                  // W2H0,W2H1,W2L0,W2L1 (8K each) = 32768
#define OF_W1TH  131072                 // W1^T hi [128n][32k] 64B rows = 8192
#define OF_W1TL  139264                 // 8192
#define OF_XRAW  147456                 // raw x staging, 2 x 14336
#define OF_B1    176128                 // 512
#define OF_B2    176640                 // 256
#define OF_E2    176896                 // 2048
#define OF_CD    178944                 // float[128][17] = 8704
#define OF_CI    187648                 // u16[128][17]   = 4352
#define SMEM_E   192000

#define XTILE_B  14336                  // 128*28*4

// XOR swizzle, 128B rows (16B granularity)
#define SWZ_W(row, w)  ((row) * 128 + ((((w) >> 2) ^ ((row) & 7)) << 4) + ((w) & 3) * 4)
#define SWZ_C(row, ch) ((row) * 128 + ((((ch)) ^ ((row) & 7)) << 4))
// XOR swizzle, 64B rows
#define SWZ64_W(row, w)  ((row) * 64 + ((((w) >> 2) ^ (((row) >> 1) & 3)) << 4) + ((w) & 3) * 4)
#define SWZ64_C(row, ch) ((row) * 64 + ((((ch)) ^ (((row) >> 1) & 3)) << 4))

#define KOUT_GRID 592

__device__ int    g_idx[B_TOTAL];
__device__ float  g_vq_part[GRID1];
__device__ float  g_rec_part[KOUT_GRID];
__device__ float  g_hd[NCODES * HID];
__device__ float  g_tbl[NCODES * IN_DIM];

// ---------------- helpers ----------------
__device__ __forceinline__ uint32_t smem_u32_of(const void* p) {
    uint32_t a;
    asm("{ .reg .u64 t; cvta.to.shared.u64 t, %1; cvt.u32.u64 %0, t; }" : "=r"(a) : "l"(p));
    return a;
}
__device__ __forceinline__ void ldsm_x4(uint32_t* r, uint32_t addr) {
    asm volatile("ldmatrix.sync.aligned.m8n8.x4.shared.b16 {%0,%1,%2,%3}, [%4];"
        : "=r"(r[0]), "=r"(r[1]), "=r"(r[2]), "=r"(r[3]) : "r"(addr));
}
__device__ __forceinline__ void mma16816(float* d, const uint32_t* a, uint32_t b0, uint32_t b1) {
    asm volatile("mma.sync.aligned.m16n8k16.row.col.f32.bf16.bf16.f32 "
        "{%0,%1,%2,%3}, {%4,%5,%6,%7}, {%8,%9}, {%0,%1,%2,%3};"
        : "+f"(d[0]), "+f"(d[1]), "+f"(d[2]), "+f"(d[3])
        : "r"(a[0]), "r"(a[1]), "r"(a[2]), "r"(a[3]), "r"(b0), "r"(b1));
}
__device__ __forceinline__ void bf16_split(float v, __nv_bfloat16& hi, __nv_bfloat16& lo) {
    hi = __float2bfloat16(v);
    lo = __float2bfloat16(v - __bfloat162float(hi));
}
__device__ __forceinline__ uint32_t pack2_split_hi(float a, float b, uint32_t& lo_out) {
    __nv_bfloat16 ha, la, hb, lb;
    bf16_split(a, ha, la); bf16_split(b, hb, lb);
    __nv_bfloat162 ph; ph.x = ha; ph.y = hb;
    __nv_bfloat162 pl; pl.x = la; pl.y = lb;
    lo_out = *(uint32_t*)&pl;
    return *(uint32_t*)&ph;
}
#define CP_ASYNC16(dst, src) \
    asm volatile("cp.async.cg.shared.global [%0], [%1], 16;" :: "r"(dst), "l"(src) : "memory")
#define CP_COMMIT() asm volatile("cp.async.commit_group;" ::: "memory")
#define CP_WAIT0()  asm volatile("cp.async.wait_group 0;" ::: "memory")

// ============================================================================
// K1: encoder — MMA enc1/enc2, distance MMA fully register-fed (bregH+bregL),
//     cp.async x staging, pair barrier between enc1/enc2
// ============================================================================
__global__ void __launch_bounds__(ETHREADS, 1)
k_encode(const float* __restrict__ x,
         const float* __restrict__ w1, const float* __restrict__ b1,
         const float* __restrict__ w2, const float* __restrict__ b2,
         const float* __restrict__ cb)
{
    extern __shared__ char smem[];
    const uint32_t smb = smem_u32_of(smem);

    float* s_b1 = (float*)(smem + OF_B1);
    float* s_b2 = (float*)(smem + OF_B2);
    float* s_e2 = (float*)(smem + OF_E2);
    float* s_cd = (float*)(smem + OF_CD);
    unsigned short* s_ci = (unsigned short*)(smem + OF_CI);

    const int tid = threadIdx.x;
    const int warp = tid >> 5, lane = tid & 31;

    // ---- issue first x-tile prefetch immediately (hides DRAM behind init) ----
    {
        const char* src = (const char*)x + (size_t)blockIdx.x * XTILE_B;
        CP_ASYNC16(smb + OF_XRAW + tid * 16, src + tid * 16);
        if (tid < 384) CP_ASYNC16(smb + OF_XRAW + (tid + 512) * 16, src + (tid + 512) * 16);
        CP_COMMIT();
    }

    // ---- init: weights, biases, e2, pads; CBH staged into HT ----
    for (int i = tid; i < HID; i += ETHREADS) s_b1[i] = b1[i];
    for (int i = tid; i < LAT; i += ETHREADS) s_b2[i] = b2[i];
    for (int i = tid; i < NCODES * 32; i += ETHREADS) {      // CBH staging
        int c = i >> 5, w = i & 31;
        uint32_t lo;
        uint32_t hi = pack2_split_hi(cb[c * LAT + 2 * w], cb[c * LAT + 2 * w + 1], lo);
        *(uint32_t*)(smem + OF_HT + SWZ_W(c, w)) = hi;
        (void)lo;
    }
    for (int i = tid; i < LAT * 64; i += ETHREADS) {         // W2^T split
        int n = i >> 6, kw = i & 63;
        uint32_t lo;
        uint32_t hi = pack2_split_hi(w2[2 * kw * LAT + n], w2[(2 * kw + 1) * LAT + n], lo);
        int khalf = kw >> 5, w = kw & 31;
        *(uint32_t*)(smem + OF_W2 + khalf * 8192 + SWZ_W(n, w))         = hi;
        *(uint32_t*)(smem + OF_W2 + 16384 + khalf * 8192 + SWZ_W(n, w)) = lo;
    }
    for (int i = tid; i < HID * 14; i += ETHREADS) {         // W1^T split
        int n = i / 14, kw = i - n * 14;
        uint32_t lo;
        uint32_t hi = pack2_split_hi(w1[2 * kw * HID + n], w1[(2 * kw + 1) * HID + n], lo);
        *(uint32_t*)(smem + OF_W1TH + SWZ64_W(n, kw)) = hi;
        *(uint32_t*)(smem + OF_W1TL + SWZ64_W(n, kw)) = lo;
    }
    for (int i = tid; i < HID * 2; i += ETHREADS) {          // W1T k-pad
        int n = i >> 1, w = 14 + (i & 1);
        *(uint32_t*)(smem + OF_W1TH + SWZ64_W(n, w)) = 0;
        *(uint32_t*)(smem + OF_W1TL + SWZ64_W(n, w)) = 0;
    }
    for (int i = tid; i < TILE_M * 2; i += ETHREADS) {       // XB k-pad (static)
        int row = i >> 1, w = 14 + (i & 1);
        *(uint32_t*)(smem + OF_XBH + SWZ64_W(row, w)) = 0;
        *(uint32_t*)(smem + OF_XBL + SWZ64_W(row, w)) = 0;
    }
    for (int c = tid; c < NCODES; c += ETHREADS) {
        float s = 0.f;
        for (int k = 0; k < LAT; k++) { float v = cb[c * LAT + k]; s = fmaf(v, v, s); }
        s_e2[c] = s;
    }
    __syncthreads();

    // mma lane-role constants
    const int g = lane >> 2, t = lane & 3;
    const int a_roff = (lane & 7) + 8 * ((lane >> 3) & 1);
    const int a_ch   = lane >> 4;
    const int b_row0 = (lane & 7) + 8 * ((lane >> 4) & 1);
    const int b_ch   = (lane >> 3) & 1;

    // ---- codebook HI fragments -> registers ----
    uint32_t bregH[4][4][2];
    #pragma unroll
    for (int pp = 0; pp < 2; pp++)
        #pragma unroll
        for (int kk = 0; kk < 4; kk++) {
            uint32_t r4[4];
            ldsm_x4(r4, smb + OF_HT + SWZ_C(warp * 32 + pp * 16 + b_row0, 2 * kk + b_ch));
            bregH[2 * pp][kk][0] = r4[0];     bregH[2 * pp][kk][1] = r4[1];
            bregH[2 * pp + 1][kk][0] = r4[2]; bregH[2 * pp + 1][kk][1] = r4[3];
        }
    __syncthreads();
    // ---- restage CBL into HT, then codebook LO fragments -> registers ----
    for (int i = tid; i < NCODES * 32; i += ETHREADS) {
        int c = i >> 5, w = i & 31;
        uint32_t lo;
        (void)pack2_split_hi(cb[c * LAT + 2 * w], cb[c * LAT + 2 * w + 1], lo);
        *(uint32_t*)(smem + OF_HT + SWZ_W(c, w)) = lo;
    }
    __syncthreads();
    uint32_t bregL[4][4][2];
    #pragma unroll
    for (int pp = 0; pp < 2; pp++)
        #pragma unroll
        for (int kk = 0; kk < 4; kk++) {
            uint32_t r4[4];
            ldsm_x4(r4, smb + OF_HT + SWZ_C(warp * 32 + pp * 16 + b_row0, 2 * kk + b_ch));
            bregL[2 * pp][kk][0] = r4[0];     bregL[2 * pp][kk][1] = r4[1];
            bregL[2 * pp + 1][kk][0] = r4[2]; bregL[2 * pp + 1][kk][1] = r4[3];
        }
    __syncthreads();   // HT now free for h tiles

    const int rbw = warp >> 1, nhf = warp & 1;
    const int R0w = rbw * 16;
    const int rA = R0w + g, rB = rA + 8;
    float vq_local = 0.f;
    int sel = 0;

    for (int tle = blockIdx.x; tle < NTILES; tle += GRID1) {
        // -------- P0: read own staged chunks, convert, store XB --------
        CP_WAIT0();
        {
            const float4* xr4 = (const float4*)(smem + OF_XRAW + sel * XTILE_B);
            float4 v = xr4[tid];
            int row = tid / 7, w4 = tid - row * 7;
            uint32_t lo0, lo1;
            uint32_t hi0 = pack2_split_hi(v.x, v.y, lo0);
            uint32_t hi1 = pack2_split_hi(v.z, v.w, lo1);
            *(uint64_t*)(smem + OF_XBH + SWZ64_W(row, 2 * w4)) =
                (uint64_t)hi0 | ((uint64_t)hi1 << 32);
            *(uint64_t*)(smem + OF_XBL + SWZ64_W(row, 2 * w4)) =
                (uint64_t)lo0 | ((uint64_t)lo1 << 32);
            if (tid < 384) {
                float4 v2 = xr4[tid + 512];
                int i2 = tid + 512;
                int row2 = i2 / 7, w42 = i2 - row2 * 7;
                uint32_t hi2 = pack2_split_hi(v2.x, v2.y, lo0);
                uint32_t hi3 = pack2_split_hi(v2.z, v2.w, lo1);
                *(uint64_t*)(smem + OF_XBH + SWZ64_W(row2, 2 * w42)) =
                    (uint64_t)hi2 | ((uint64_t)hi3 << 32);
                *(uint64_t*)(smem + OF_XBL + SWZ64_W(row2, 2 * w42)) =
                    (uint64_t)lo0 | ((uint64_t)lo1 << 32);
            }
        }
        __syncthreads();   // A

        // prefetch next tile into the other staging buffer
        {
            int nt = tle + GRID1;
            if (nt < NTILES) {
                const char* src = (const char*)x + (size_t)nt * XTILE_B;
                uint32_t dst = smb + OF_XRAW + (sel ^ 1) * XTILE_B;
                CP_ASYNC16(dst + tid * 16, src + tid * 16);
                if (tid < 384) CP_ASYNC16(dst + (tid + 512) * 16, src + (tid + 512) * 16);
            }
            CP_COMMIT();
        }
        sel ^= 1;

        // -------- P1: enc1 MMA: h = relu(x @ W1 + b1) -> HT tiles --------
        {
            uint32_t xH[2][4], xL[2][4];
            #pragma unroll
            for (int kk = 0; kk < 2; kk++) {
                uint32_t offA = SWZ64_C(R0w + a_roff, 2 * kk + a_ch);
                ldsm_x4(xH[kk], smb + OF_XBH + offA);
                ldsm_x4(xL[kk], smb + OF_XBL + offA);
            }
            #pragma unroll
            for (int half = 0; half < 2; half++) {
                float acc[4][4];
                #pragma unroll
                for (int nb = 0; nb < 4; nb++)
                    #pragma unroll
                    for (int u = 0; u < 4; u++) acc[nb][u] = 0.f;

                #pragma unroll
                for (int kk = 0; kk < 2; kk++) {
                    #pragma unroll
                    for (int p2 = 0; p2 < 2; p2++) {
                        int pp = half * 2 + p2;
                        int nrow = nhf * 64 + pp * 16 + b_row0;
                        uint32_t offB = SWZ64_C(nrow, 2 * kk + b_ch);
                        uint32_t bH[4], bL[4];
                        ldsm_x4(bH, smb + OF_W1TH + offB);
                        ldsm_x4(bL, smb + OF_W1TL + offB);
                        mma16816(acc[2 * p2], xH[kk], bH[0], bH[1]);
                        mma16816(acc[2 * p2], xH[kk], bL[0], bL[1]);
                        mma16816(acc[2 * p2], xL[kk], bH[0], bH[1]);
                        mma16816(acc[2 * p2 + 1], xH[kk], bH[2], bH[3]);
                        mma16816(acc[2 * p2 + 1], xH[kk], bL[2], bL[3]);
                        mma16816(acc[2 * p2 + 1], xL[kk], bH[2], bH[3]);
                    }
                }
                #pragma unroll
                for (int nb = 0; nb < 4; nb++) {
                    int gnb = half * 4 + nb;
                    int c = nhf * 64 + gnb * 8 + 2 * t;
                    float bb0 = s_b1[c], bb1 = s_b1[c + 1];
                    int w = gnb * 4 + t;
                    float h00 = fmaxf(acc[nb][0] + bb0, 0.f);
                    float h01 = fmaxf(acc[nb][1] + bb1, 0.f);
                    float h10 = fmaxf(acc[nb][2] + bb0, 0.f);
                    float h11 = fmaxf(acc[nb][3] + bb1, 0.f);
                    uint32_t lo;
                    uint32_t hi = pack2_split_hi(h00, h01, lo);
                    *(uint32_t*)(smem + OF_HT + nhf * 16384 + SWZ_W(rA, w)) = hi;
                    *(uint32_t*)(smem + OF_HT + 32768 + nhf * 16384 + SWZ_W(rA, w)) = lo;
                    hi = pack2_split_hi(h10, h11, lo);
                    *(uint32_t*)(smem + OF_HT + nhf * 16384 + SWZ_W(rB, w)) = hi;
                    *(uint32_t*)(smem + OF_HT + 32768 + nhf * 16384 + SWZ_W(rB, w)) = lo;
                }
            }
        }
        // pair barrier: h producers == consumers (warps 2*rbw, 2*rbw+1)
        asm volatile("bar.sync %0, 64;" :: "r"(rbw + 1) : "memory");

        // -------- P2: enc2 MMA: z = h @ W2 + b2 -> ZB; fold ||z||^2 into vq --------
        {
            const int a_row2 = R0w + a_roff;
            float acc2[4][4];
            #pragma unroll
            for (int nb = 0; nb < 4; nb++)
                #pragma unroll
                for (int u = 0; u < 4; u++) acc2[nb][u] = 0.f;

            #pragma unroll
            for (int khalf = 0; khalf < 2; khalf++) {
                #pragma unroll
                for (int kk = 0; kk < 4; kk++) {
                    uint32_t aH[4], aL[4];
                    uint32_t offA = SWZ_C(a_row2, 2 * kk + a_ch);
                    ldsm_x4(aH, smb + OF_HT + khalf * 16384 + offA);
                    ldsm_x4(aL, smb + OF_HT + 32768 + khalf * 16384 + offA);
                    #pragma unroll
                    for (int pp = 0; pp < 2; pp++) {
                        int nrow = nhf * 32 + pp * 16 + b_row0;
                        uint32_t offB = SWZ_C(nrow, 2 * kk + b_ch);
                        uint32_t bH[4], bL[4];
                        ldsm_x4(bH, smb + OF_W2 + khalf * 8192 + offB);
                        ldsm_x4(bL, smb + OF_W2 + 16384 + khalf * 8192 + offB);
                        mma16816(acc2[2 * pp], aH, bH[0], bH[1]);
                        mma16816(acc2[2 * pp], aH, bL[0], bL[1]);
                        mma16816(acc2[2 * pp], aL, bH[0], bH[1]);
                        mma16816(acc2[2 * pp + 1], aH, bH[2], bH[3]);
                        mma16816(acc2[2 * pp + 1], aH, bL[2], bL[3]);
                        mma16816(acc2[2 * pp + 1], aL, bH[2], bH[3]);
                    }
                }
            }
            float z2sum = 0.f;
            #pragma unroll
            for (int nb = 0; nb < 4; nb++) {
                int c0 = nhf * 32 + nb * 8 + 2 * t;
                int w = c0 >> 1;
                float bb0 = s_b2[c0], bb1 = s_b2[c0 + 1];
                float z00 = acc2[nb][0] + bb0, z01 = acc2[nb][1] + bb1;
                float z10 = acc2[nb][2] + bb0, z11 = acc2[nb][3] + bb1;
                z2sum = fmaf(z00, z00, fmaf(z01, z01, z2sum));
                z2sum = fmaf(z10, z10, fmaf(z11, z11, z2sum));
                uint32_t lo;
                uint32_t hi = pack2_split_hi(z00, z01, lo);
                *(uint32_t*)(smem + OF_ZBH + SWZ_W(rA, w)) = hi;
                *(uint32_t*)(smem + OF_ZBL + SWZ_W(rA, w)) = lo;
                hi = pack2_split_hi(z10, z11, lo);
                *(uint32_t*)(smem + OF_ZBH + SWZ_W(rB, w)) = hi;
                *(uint32_t*)(smem + OF_ZBL + SWZ_W(rB, w)) = lo;
            }
            vq_local += z2sum;
        }
        __syncthreads();   // C

        // -------- P3: distance MMA, fully register-fed B operands --------
        #pragma unroll 1
        for (int rb = 0; rb < 8; rb++) {
            const int a_row3 = rb * 16 + a_roff;
            uint32_t afH[2][4], afL[2][4];
            {
                uint32_t off = SWZ_C(a_row3, a_ch);
                ldsm_x4(afH[0], smb + OF_ZBH + off);
                ldsm_x4(afL[0], smb + OF_ZBL + off);
            }
            float acc3[4][4];
            #pragma unroll
            for (int nb = 0; nb < 4; nb++)
                #pragma unroll
                for (int u = 0; u < 4; u++) acc3[nb][u] = 0.f;

            #pragma unroll
            for (int kk = 0; kk < 4; kk++) {
                int cur = kk & 1;
                if (kk < 3) {
                    uint32_t off = SWZ_C(a_row3, 2 * (kk + 1) + a_ch);
                    ldsm_x4(afH[cur ^ 1], smb + OF_ZBH + off);
                    ldsm_x4(afL[cur ^ 1], smb + OF_ZBL + off);
                }
                #pragma unroll
                for (int nb = 0; nb < 4; nb++) {
                    mma16816(acc3[nb], afH[cur], bregH[nb][kk][0], bregH[nb][kk][1]);  // zH*eH
                    mma16816(acc3[nb], afL[cur], bregH[nb][kk][0], bregH[nb][kk][1]);  // zL*eH
                    mma16816(acc3[nb], afH[cur], bregL[nb][kk][0], bregL[nb][kk][1]);  // zH*eL
                }
            }
            float mA = 3.4e38f, mB = 3.4e38f; int iA = 0, iB = 0;
            #pragma unroll
            for (int nb = 0; nb < 4; nb++) {
                int c0 = warp * 32 + nb * 8 + 2 * t;
                float e0 = s_e2[c0], e1 = s_e2[c0 + 1];
                float d00 = fmaf(-2.f, acc3[nb][0], e0);
                float d01 = fmaf(-2.f, acc3[nb][1], e1);
                float d10 = fmaf(-2.f, acc3[nb][2], e0);
                float d11 = fmaf(-2.f, acc3[nb][3], e1);
                if (d00 < mA) { mA = d00; iA = c0; }
                if (d01 < mA) { mA = d01; iA = c0 + 1; }
                if (d10 < mB) { mB = d10; iB = c0; }
                if (d11 < mB) { mB = d11; iB = c0 + 1; }
            }
            #pragma unroll
            for (int off = 1; off <= 2; off <<= 1) {
                float ov = __shfl_xor_sync(0xffffffffu, mA, off);
                int   oi = __shfl_xor_sync(0xffffffffu, iA, off);
                if (ov < mA || (ov == mA && oi < iA)) { mA = ov; iA = oi; }
                ov = __shfl_xor_sync(0xffffffffu, mB, off);
                oi = __shfl_xor_sync(0xffffffffu, iB, off);
                if (ov < mB || (ov == mB && oi < iB)) { mB = ov; iB = oi; }
            }
            if (t == 0) {
                s_cd[(rb * 16 + g) * 17 + warp]     = mA;
                s_ci[(rb * 16 + g) * 17 + warp]     = (unsigned short)iA;
                s_cd[(rb * 16 + 8 + g) * 17 + warp] = mB;
                s_ci[(rb * 16 + 8 + g) * 17 + warp] = (unsigned short)iB;
            }
        }
        __syncthreads();   // D

        // -------- P4: per-row scan of 16 warp-candidates; vq += d_min --------
        if (tid < TILE_M) {
            const float* rowd = s_cd + tid * 17;
            const unsigned short* rowi = s_ci + tid * 17;
            float best = rowd[0];
            int   bi   = rowi[0];
            #pragma unroll
            for (int w = 1; w < EWARPS; w++) {
                float dw = rowd[w];
                if (dw < best) { best = dw; bi = rowi[w]; }
            }
            g_idx[tle * TILE_M + tid] = bi;
            vq_local += best;
        }
        // no barrier: next P0 writes only XB(=ZB), dead since D
    }

    // ---- reduce vq ----
    #pragma unroll
    for (int off = 16; off; off >>= 1) vq_local += __shfl_down_sync(0xffffffffu, vq_local, off);
    __syncthreads();
    float* s_red = (float*)(smem + OF_CD);
    if (lane == 0) s_red[warp] = vq_local;
    __syncthreads();
    if (tid == 0) {
        float s = 0.f;
        for (int w = 0; w < EWARPS; w++) s += s_red[w];
        g_vq_part[blockIdx.x] = s;
    }
}

// ============================================================================
// decoder table for 512 codes (exact fp32)
// ============================================================================
__global__ void k_hd(const float* __restrict__ cb,
                     const float* __restrict__ dw1, const float* __restrict__ db1)
{
    int gid = blockIdx.x * blockDim.x + threadIdx.x;
    int c = gid >> 7, j = gid & 127;
    float acc = db1[j];
    const float* q = cb + c * LAT;
    #pragma unroll 8
    for (int k = 0; k < LAT; k++) acc = fmaf(q[k], dw1[k * HID + j], acc);
    g_hd[gid] = fmaxf(acc, 0.f);
}

__global__ void k_tbl(const float* __restrict__ dw2, const float* __restrict__ db2)
{
    int gid = blockIdx.x * blockDim.x + threadIdx.x;
    int c = gid / IN_DIM, j = gid - c * IN_DIM;
    float acc = db2[j];
    const float* hd = g_hd + c * HID;
    #pragma unroll 8
    for (int k = 0; k < HID; k++) acc = fmaf(hd[k], dw2[k * IN_DIM + j], acc);
    g_tbl[gid] = acc;
}

// ============================================================================
// k_out: gather recon from table, write out, recon-loss partials
// ============================================================================
#define OUT_THREADS 512
__global__ void __launch_bounds__(OUT_THREADS)
k_out(const float* __restrict__ x, float* __restrict__ out)
{
    const int total4 = B_TOTAL * (IN_DIM / 4);
    const float4* x4 = (const float4*)x;
    float4* o4 = (float4*)out;
    const float4* t4 = (const float4*)g_tbl;

    float rec = 0.f;
    for (int f4 = blockIdx.x * OUT_THREADS + threadIdx.x; f4 < total4;
         f4 += KOUT_GRID * OUT_THREADS) {
        int row = f4 / 7;
        int w = f4 - row * 7;
        int idx = g_idx[row];
        float4 tv = t4[idx * 7 + w];
        float4 xv = x4[f4];
        o4[f4] = tv;
        float d0 = tv.x - xv.x, d1 = tv.y - xv.y, d2 = tv.z - xv.z, d3 = tv.w - xv.w;
        rec = fmaf(d0, d0, fmaf(d1, d1, fmaf(d2, d2, fmaf(d3, d3, rec))));
    }
    __shared__ float s_red[OUT_THREADS / 32];
    #pragma unroll
    for (int off = 16; off; off >>= 1) rec += __shfl_down_sync(0xffffffffu, rec, off);
    if ((threadIdx.x & 31) == 0) s_red[threadIdx.x >> 5] = rec;
    __syncthreads();
    if (threadIdx.x == 0) {
        float s = 0.f;
        for (int w = 0; w < OUT_THREADS / 32; w++) s += s_red[w];
        g_rec_part[blockIdx.x] = s;
    }
}

// ============================================================================
// finalize scalar losses
// ============================================================================
__global__ void k_final(float* __restrict__ out)
{
    if (threadIdx.x == 0) {
        double vs = 0.0, rs = 0.0;
        for (int i = 0; i < GRID1; i++) vs += (double)g_vq_part[i];
        for (int i = 0; i < KOUT_GRID; i++) rs += (double)g_rec_part[i];
        out[(long)B_TOTAL * IN_DIM]     = (float)(rs / ((double)B_TOTAL * IN_DIM));
        out[(long)B_TOTAL * IN_DIM + 1] = (float)(1.25 * vs / ((double)B_TOTAL * LAT));
    }
}

// ============================================================================
extern "C" void kernel_launch(void* const* d_in, const int* in_sizes, int n_in,
                              void* d_out, int out_size)
{
    const float* x    = (const float*)d_in[0];
    const float* ew1  = (const float*)d_in[1];
    const float* eb1  = (const float*)d_in[2];
    const float* ew2  = (const float*)d_in[3];
    const float* eb2  = (const float*)d_in[4];
    const float* cb   = (const float*)d_in[5];
    const float* dw1  = (const float*)d_in[6];
    const float* db1  = (const float*)d_in[7];
    const float* dw2  = (const float*)d_in[8];
    const float* db2  = (const float*)d_in[9];
    float* out = (float*)d_out;

    cudaFuncSetAttribute(k_encode, cudaFuncAttributeMaxDynamicSharedMemorySize, SMEM_E);

    k_hd<<<(NCODES * HID) / 256, 256>>>(cb, dw1, db1);
    k_tbl<<<(NCODES * IN_DIM) / 256, 256>>>(dw2, db2);
    k_encode<<<GRID1, ETHREADS, SMEM_E>>>(x, ew1, eb1, ew2, eb2, cb);
    k_out<<<KOUT_GRID, OUT_THREADS>>>(x, out);
    k_final<<<1, 32>>>(out);
}